// round 13
// baseline (speedup 1.0000x reference)
#include <cuda_runtime.h>
#include <cuda_fp16.h>
#include <cstdint>

// Problem constants (fixed shape: B=8, S=8192, D=256, K=2048)
#define N_PTS   65536
#define D_DIM   256
#define K_CODES 2048

#define DECAY_F 0.99f
#define OMD_F   0.01f
#define EPS_F   1e-6f

// Output layout (float32, concatenated in reference return order)
#define OFF_Q   0
#define OFF_IND (N_PTS * D_DIM)
#define OFF_CS  (OFF_IND + N_PTS)
#define OFF_AVG (OFF_CS + K_CODES)
#define OFF_EMB (OFF_AVG + K_CODES * D_DIM)

// ---------------------------------------------------------------------------
// Device scratch (no runtime allocations allowed)
// ---------------------------------------------------------------------------
__device__ int   g_idx[N_PTS];
__device__ float g_counts[K_CODES];
__device__ __align__(16) float g_esum[K_CODES * D_DIM];
__device__ float g_ehn[K_CODES];     // 0.5 * ||e_k||^2 (fp32)
__device__ float g_total;
// fp16 2-limb split of embed: e = e1 + e2 (exact to ~22 mantissa bits)
__device__ __align__(16) __half g_e1[K_CODES * D_DIM];
__device__ __align__(16) __half g_e2[K_CODES * D_DIM];

// ---------------------------------------------------------------------------
// PTX helpers
// ---------------------------------------------------------------------------
__device__ __forceinline__ uint32_t smem_u32(const void* p) {
    uint32_t a;
    asm("{ .reg .u64 t; cvta.to.shared.u64 t, %1; cvt.u32.u64 %0, t; }"
        : "=r"(a) : "l"(p));
    return a;
}

#define CP_ASYNC16(dst, src) \
    asm volatile("cp.async.cg.shared.global [%0], [%1], 16;" \
                 :: "r"(dst), "l"(src) : "memory")
#define CP_ASYNC_COMMIT() asm volatile("cp.async.commit_group;" ::: "memory")
#define CP_ASYNC_WAIT0()  asm volatile("cp.async.wait_group 0;" ::: "memory")
#define CP_ASYNC_WAIT1()  asm volatile("cp.async.wait_group 1;" ::: "memory")

__device__ __forceinline__ void ldm_x4(uint32_t* r, uint32_t addr) {
    asm volatile("ldmatrix.sync.aligned.m8n8.x4.shared.b16 {%0,%1,%2,%3}, [%4];"
        : "=r"(r[0]), "=r"(r[1]), "=r"(r[2]), "=r"(r[3]) : "r"(addr));
}

__device__ __forceinline__ void mma16816(float* c, const uint32_t* a,
                                         const uint32_t* b) {
    asm volatile(
        "mma.sync.aligned.m16n8k16.row.col.f32.f16.f16.f32 "
        "{%0,%1,%2,%3}, {%4,%5,%6,%7}, {%8,%9}, {%0,%1,%2,%3};"
        : "+f"(c[0]), "+f"(c[1]), "+f"(c[2]), "+f"(c[3])
        : "r"(a[0]), "r"(a[1]), "r"(a[2]), "r"(a[3]), "r"(b[0]), "r"(b[1]));
}

// sm_90+ vectorized global reduction (4x fewer L2 atomic ops)
__device__ __forceinline__ void red_add_v4(float* p, float4 v) {
    asm volatile("red.global.add.v4.f32 [%0], {%1, %2, %3, %4};"
                 :: "l"(p), "f"(v.x), "f"(v.y), "f"(v.z), "f"(v.w) : "memory");
}

// ---------------------------------------------------------------------------
// Zero scratch (graph replays must be deterministic)
// ---------------------------------------------------------------------------
__global__ void zero_kernel() {
    int i = blockIdx.x * blockDim.x + threadIdx.x;
    if (i < K_CODES * D_DIM) g_esum[i] = 0.0f;
    if (i < K_CODES)         g_counts[i] = 0.0f;
    if (i == 0)              g_total = 0.0f;
}

// ---------------------------------------------------------------------------
// fp16 2-limb exact split of embed
// ---------------------------------------------------------------------------
__global__ __launch_bounds__(256)
void split_e_kernel(const float* __restrict__ e) {
    const int i = blockIdx.x * 256 + threadIdx.x;   // pair index
    const int n2 = K_CODES * D_DIM / 2;
    if (i >= n2) return;
    float2 v = ((const float2*)e)[i];
    __half a1 = __float2half_rn(v.x);
    __half b1 = __float2half_rn(v.y);
    __half a2 = __float2half_rn(v.x - __half2float(a1));
    __half b2 = __float2half_rn(v.y - __half2float(b1));
    ((__half2*)g_e1)[i] = __halves2half2(a1, b1);
    ((__half2*)g_e2)[i] = __halves2half2(a2, b2);
}

// ---------------------------------------------------------------------------
// 0.5*||e_k||^2 (fp32, from original embed)
// ---------------------------------------------------------------------------
__global__ void ehn_kernel(const float* __restrict__ embed) {
    const int k = blockIdx.x;
    const int t = threadIdx.x;  // 0..63
    float4 v = *(const float4*)(embed + (size_t)k * D_DIM + t * 4);
    float s = v.x * v.x + v.y * v.y + v.z * v.z + v.w * v.w;
#pragma unroll
    for (int o = 16; o > 0; o >>= 1) s += __shfl_xor_sync(0xffffffffu, s, o);
    __shared__ float sh[2];
    if ((t & 31) == 0) sh[t >> 5] = s;
    __syncthreads();
    if (t == 0) g_ehn[k] = 0.5f * (sh[0] + sh[1]);
}

// ---------------------------------------------------------------------------
// HMMA argmin kernel (256 threads, 8 warps = 4 warp_m x 2 warp_n).
//   argmin_k ||x-e_k||^2 == argmax_k (x.e_k - ||e_k||^2/2).
//   Per CTA: 128 rows. x split to fp16 limbs IN-KERNEL, resident in smem
//   (128 KB, both limbs, XOR-swizzled). B (embed limbs) streamed in
//   [128 codes x 64 d] double-buffered cp.async stages (64 KB).
//   16 code tiles x 4 chunks = 64 stages; per k16 step: 3 limb products
//   (a1b1, a1b2, a2b1) via mma.sync.m16n8k16 into fp32 regs.
//   DEFERRED EPILOGUE: two C banks (tile&1). Tile t's epilogue runs during
//   the FIRST stage of tile t+1, after that stage's MMAs are issued — so it
//   never waits on tensor-pipe drain and its ALU overlaps the MMA backlog.
//   Per-bank accumulation order identical to prior rounds (bit-stable).
// ---------------------------------------------------------------------------
#define A_LIMB_STRIDE 65536       // 128 rows x 512 B
#define B_OFF  131072             // A occupies [0, 128KB)
#define B_STG  32768              // per stage: 2 limbs x 128 x 128B
#define DSMEM_SZ (B_OFF + 2 * B_STG)   // 196608

__device__ __forceinline__ void issue_B(int s, uint32_t Bb, int tid) {
    const int tile = s >> 2, ch = s & 3, buf = s & 1;
#pragma unroll
    for (int i = 0; i < 8; i++) {
        const int idx = i * 256 + tid;        // 0..2047
        const int limb = idx >> 10;
        const int rem  = idx & 1023;
        const int n    = rem >> 3;            // 0..127
        const int kc   = rem & 7;             // 16B chunk within 64-d row
        const __half* src = (limb ? g_e2 : g_e1) +
            (size_t)(tile * 128 + n) * D_DIM + ch * 64 + kc * 8;
        const uint32_t dst = Bb + buf * B_STG + limb * 16384 +
            n * 128 + ((kc ^ (n & 7)) * 16);
        CP_ASYNC16(dst, src);
    }
    CP_ASYNC_COMMIT();
}

__global__ __launch_bounds__(256, 1)
void argmin_mma_kernel(const float* __restrict__ x) {
    extern __shared__ char dsm[];
    __shared__ float s_v[256];
    __shared__ int   s_i[256];

    const int tid    = threadIdx.x;
    const int wid    = tid >> 5;
    const int lane   = tid & 31;
    const int warp_m = wid & 3;     // 32 rows each
    const int warp_n = wid >> 2;    // 64 cols each (0..1)
    const int row0   = blockIdx.x * 128;

    const uint32_t Ab = smem_u32(dsm);
    const uint32_t Bb = Ab + B_OFF;

    // ---- Phase 1: load x block, split to fp16 limbs, store swizzled smem ----
    // A layout per limb: [m][512B row], 16B chunk index swizzled:
    //   swc = (chunk & 24) | ((chunk ^ m) & 7)
#pragma unroll 4
    for (int j = 0; j < 32; j++) {
        const int f  = j * 256 + tid;         // float4 index, 0..8191
        const int m  = f >> 6;                // 0..127
        const int k0 = (f & 63) * 4;          // 0..252
        float4 v = __ldg((const float4*)(x + (size_t)(row0 + m) * D_DIM + k0));
        __half hx1 = __float2half_rn(v.x), hy1 = __float2half_rn(v.y);
        __half hz1 = __float2half_rn(v.z), hw1 = __float2half_rn(v.w);
        __half hx2 = __float2half_rn(v.x - __half2float(hx1));
        __half hy2 = __float2half_rn(v.y - __half2float(hy1));
        __half hz2 = __float2half_rn(v.z - __half2float(hz1));
        __half hw2 = __float2half_rn(v.w - __half2float(hw1));
        const int chunk = k0 >> 3;
        const int swc = (chunk & 24) | ((chunk ^ m) & 7);
        const uint32_t off = (uint32_t)(m * 512 + swc * 16 + (k0 & 7) * 2);
        __half2* p1 = (__half2*)(dsm + off);
        p1[0] = __halves2half2(hx1, hy1);
        p1[1] = __halves2half2(hz1, hw1);
        __half2* p2 = (__half2*)(dsm + A_LIMB_STRIDE + off);
        p2[0] = __halves2half2(hx2, hy2);
        p2[1] = __halves2half2(hz2, hw2);
    }
    __syncthreads();

    // ---- Phase 2: main loop over 64 stages, C ping-pong across tiles ----
    float C[2][2][8][4];   // [bank][mf][nf][q]
#pragma unroll
    for (int bk = 0; bk < 2; bk++)
#pragma unroll
        for (int mf = 0; mf < 2; mf++)
#pragma unroll
            for (int nf = 0; nf < 8; nf++)
#pragma unroll
                for (int q = 0; q < 4; q++) C[bk][mf][nf][q] = 0.0f;

    float bestv[4];
    int   besti[4];
#pragma unroll
    for (int q = 0; q < 4; q++) { bestv[q] = -3.402823466e38f; besti[q] = 0; }

    // Deferred epilogue for finished tile pc (bank pc&1): subtract 0.5||e||^2,
    // update running argmax, zero the bank for tile pc+2.
    auto epilogue = [&](int pc) {
        const int bk = pc & 1;
        const int cb = pc * 128 + warp_n * 64 + (lane & 3) * 2;
#pragma unroll
        for (int nf = 0; nf < 8; nf++) {
            const int col = cb + nf * 8;
            const float2 h = __ldg((const float2*)(g_ehn + col));
#pragma unroll
            for (int mf = 0; mf < 2; mf++) {
                const int sl = mf * 2;
                const float s0 = C[bk][mf][nf][0] - h.x;
                const float s1 = C[bk][mf][nf][1] - h.y;
                const float s2 = C[bk][mf][nf][2] - h.x;
                const float s3 = C[bk][mf][nf][3] - h.y;
                // ascending col within thread + strict > : lowest col wins
                if (s0 > bestv[sl])     { bestv[sl] = s0;     besti[sl] = col; }
                if (s1 > bestv[sl])     { bestv[sl] = s1;     besti[sl] = col + 1; }
                if (s2 > bestv[sl + 1]) { bestv[sl + 1] = s2; besti[sl + 1] = col; }
                if (s3 > bestv[sl + 1]) { bestv[sl + 1] = s3; besti[sl + 1] = col + 1; }
                C[bk][mf][nf][0] = 0.0f; C[bk][mf][nf][1] = 0.0f;
                C[bk][mf][nf][2] = 0.0f; C[bk][mf][nf][3] = 0.0f;
            }
        }
    };

    issue_B(0, Bb, tid);

    for (int s = 0; s < 64; s++) {
        const int tile = s >> 2, ch = s & 3, buf = s & 1;
        if (s < 63) { issue_B(s + 1, Bb, tid); CP_ASYNC_WAIT1(); }
        else        { CP_ASYNC_WAIT0(); }
        __syncthreads();

        const int bk = tile & 1;
        const uint32_t Bs = Bb + buf * B_STG;
#pragma unroll
        for (int ks = 0; ks < 4; ks++) {
            // A fragments: [limb][mf] x4 (m16 x k16)
            uint32_t a[2][2][4];
#pragma unroll
            for (int limb = 0; limb < 2; limb++)
#pragma unroll
                for (int mf = 0; mf < 2; mf++) {
                    const int m = warp_m * 32 + mf * 16 + (lane & 15);
                    const int chunk = ch * 8 + ks * 2 + ((lane >> 4) & 1);
                    const int swc = (chunk & 24) | ((chunk ^ m) & 7);
                    ldm_x4(a[limb][mf],
                           Ab + limb * A_LIMB_STRIDE + m * 512 + swc * 16);
                }
            // B fragments: [limb][nf] x2, loaded as x4 pairs (n16 x k16)
            uint32_t b[2][8][2];
#pragma unroll
            for (int limb = 0; limb < 2; limb++)
#pragma unroll
                for (int nfp = 0; nfp < 4; nfp++) {
                    const int n = warp_n * 64 + nfp * 16 + (lane & 7) +
                                  ((lane >> 4) & 1) * 8;
                    const int kc = ks * 2 + ((lane >> 3) & 1);
                    uint32_t r[4];
                    ldm_x4(r, Bs + limb * 16384 + n * 128 +
                              ((kc ^ (n & 7)) * 16));
                    b[limb][nfp * 2    ][0] = r[0];
                    b[limb][nfp * 2    ][1] = r[1];
                    b[limb][nfp * 2 + 1][0] = r[2];
                    b[limb][nfp * 2 + 1][1] = r[3];
                }
            // 3 limb products per (mf, nf) into bank bk
#pragma unroll
            for (int mf = 0; mf < 2; mf++)
#pragma unroll
                for (int nf = 0; nf < 8; nf++) {
                    mma16816(C[bk][mf][nf], a[0][mf], b[0][nf]);
                    mma16816(C[bk][mf][nf], a[0][mf], b[1][nf]);
                    mma16816(C[bk][mf][nf], a[1][mf], b[0][nf]);
                }
        }

        // Deferred epilogue: previous tile's bank, after this stage's MMAs
        // are in flight (its MMAs finished a full stage ago — no drain wait).
        if (ch == 0 && tile >= 1) epilogue(tile - 1);
    }

    epilogue(15);   // final tile (bank 1); its MMAs drain during final redn

    // ---- Final reduction ----
    // Per-row candidates live in a quartet of lanes (same lane>>2).
#pragma unroll
    for (int sl = 0; sl < 4; sl++) {
        float v = bestv[sl];
        int   ii = besti[sl];
#pragma unroll
        for (int msk = 1; msk <= 2; msk <<= 1) {
            const float ov = __shfl_xor_sync(0xffffffffu, v, msk);
            const int   oi = __shfl_xor_sync(0xffffffffu, ii, msk);
            if (ov > v || (ov == v && oi < ii)) { v = ov; ii = oi; }
        }
        if ((lane & 3) == 0) {
            const int lr = warp_m * 32 + (sl >> 1) * 16 + (sl & 1) * 8 + (lane >> 2);
            s_v[warp_n * 128 + lr] = v;
            s_i[warp_n * 128 + lr] = ii;
        }
    }
    __syncthreads();
    if (tid < 128) {
        float v0 = s_v[tid];        int i0 = s_i[tid];
        const float v1 = s_v[128 + tid];
        const int   i1 = s_i[128 + tid];
        if (v1 > v0 || (v1 == v0 && i1 < i0)) { v0 = v1; i0 = i1; }
        g_idx[row0 + tid] = i0;
    }
}

// ---------------------------------------------------------------------------
// Gather quantize rows + scatter counts/embed_sum.
// Vectorized L2 reductions (red.global.add.v4.f32): 4x fewer atomic ops.
// ---------------------------------------------------------------------------
__global__ __launch_bounds__(256)
void gather_scatter_kernel(const float* __restrict__ x,
                           const float* __restrict__ embed,
                           float* __restrict__ out) {
    const int row = blockIdx.x * 4 + (threadIdx.x >> 6);
    const int t   = threadIdx.x & 63;
    const int k   = g_idx[row];
    const int dof = t * 4;

    float4 e = __ldg((const float4*)(embed + (size_t)k * D_DIM + dof));
    *(float4*)(out + OFF_Q + (size_t)row * D_DIM + dof) = e;

    float4 xv = __ldg((const float4*)(x + (size_t)row * D_DIM + dof));
    red_add_v4(&g_esum[k * D_DIM + dof], xv);

    if (t == 0) {
        out[OFF_IND + row] = (float)k;
        atomicAdd(&g_counts[k], 1.0f);
    }
}

// ---------------------------------------------------------------------------
// Finalize 1: new_cluster_size + total (single block)
// ---------------------------------------------------------------------------
__global__ void finalize1_kernel(const float* __restrict__ cluster_size,
                                 float* __restrict__ out) {
    const int t = threadIdx.x;  // 1024 threads
    float s = 0.0f;
    for (int i = t; i < K_CODES; i += 1024) {
        const float v = cluster_size[i] * DECAY_F + OMD_F * g_counts[i];
        out[OFF_CS + i] = v;
        s += v;
    }
#pragma unroll
    for (int o = 16; o > 0; o >>= 1) s += __shfl_xor_sync(0xffffffffu, s, o);
    __shared__ float sh[32];
    if ((t & 31) == 0) sh[t >> 5] = s;
    __syncthreads();
    if (t < 32) {
        float v = sh[t];
#pragma unroll
        for (int o = 16; o > 0; o >>= 1) v += __shfl_xor_sync(0xffffffffu, v, o);
        if (t == 0) g_total = v;
    }
}

// ---------------------------------------------------------------------------
// Finalize 2: new_embed_avg + new_embed (grid = K blocks x 64 threads)
// ---------------------------------------------------------------------------
__global__ void finalize2_kernel(const float* __restrict__ embed_avg,
                                 float* __restrict__ out) {
    const int k = blockIdx.x;
    const int t = threadIdx.x;  // 0..63
    const float ncs   = out[OFF_CS + k];
    const float total = g_total;
    const float smoothed = (ncs + EPS_F) / (total + EPS_F * (float)K_CODES) * total;

    const int base = k * D_DIM + t * 4;
    float4 ea = *(const float4*)(embed_avg + base);
    float4 es = *(const float4*)(&g_esum[base]);
    float4 nav;
    nav.x = ea.x * DECAY_F + OMD_F * es.x;
    nav.y = ea.y * DECAY_F + OMD_F * es.y;
    nav.z = ea.z * DECAY_F + OMD_F * es.z;
    nav.w = ea.w * DECAY_F + OMD_F * es.w;
    *(float4*)(out + OFF_AVG + base) = nav;

    float4 ne;
    ne.x = nav.x / smoothed;
    ne.y = nav.y / smoothed;
    ne.z = nav.z / smoothed;
    ne.w = nav.w / smoothed;
    *(float4*)(out + OFF_EMB + base) = ne;
}

// ---------------------------------------------------------------------------
// Launch
// ---------------------------------------------------------------------------
extern "C" void kernel_launch(void* const* d_in, const int* in_sizes, int n_in,
                              void* d_out, int out_size) {
    const float* x         = (const float*)d_in[0];  // [B,S,D] fp32
    const float* embed     = (const float*)d_in[1];  // [K,D]
    const float* csize     = (const float*)d_in[2];  // [K]
    const float* embed_avg = (const float*)d_in[3];  // [K,D]
    float* out = (float*)d_out;

    static int smem_set = 0;
    if (!smem_set) {
        cudaFuncSetAttribute(argmin_mma_kernel,
                             cudaFuncAttributeMaxDynamicSharedMemorySize,
                             DSMEM_SZ);
        smem_set = 1;
    }

    zero_kernel<<<(K_CODES * D_DIM + 255) / 256, 256>>>();
    split_e_kernel<<<(K_CODES * D_DIM / 2 + 255) / 256, 256>>>(embed);
    ehn_kernel<<<K_CODES, 64>>>(embed);
    argmin_mma_kernel<<<N_PTS / 128, 256, DSMEM_SZ>>>(x);
    gather_scatter_kernel<<<N_PTS / 4, 256>>>(x, embed, out);
    finalize1_kernel<<<1, 1024>>>(csize, out);
    finalize2_kernel<<<K_CODES, 64>>>(embed_avg, out);
}

// round 14
// speedup vs baseline: 2.5277x; 2.5277x over previous
#include <cuda_runtime.h>
#include <cuda_fp16.h>
#include <cstdint>

// Problem constants (fixed shape: B=8, S=8192, D=256, K=2048)
#define N_PTS   65536
#define D_DIM   256
#define K_CODES 2048

#define DECAY_F 0.99f
#define OMD_F   0.01f
#define EPS_F   1e-6f

// Output layout (float32, concatenated in reference return order)
#define OFF_Q   0
#define OFF_IND (N_PTS * D_DIM)
#define OFF_CS  (OFF_IND + N_PTS)
#define OFF_AVG (OFF_CS + K_CODES)
#define OFF_EMB (OFF_AVG + K_CODES * D_DIM)

// ---------------------------------------------------------------------------
// Device scratch (no runtime allocations allowed)
// ---------------------------------------------------------------------------
__device__ int   g_idx[N_PTS];
__device__ float g_counts[K_CODES];
__device__ __align__(16) float g_esum[K_CODES * D_DIM];
__device__ float g_ehn[K_CODES];     // 0.5 * ||e_k||^2 (fp32)
__device__ float g_total;
// fp16 2-limb split of embed: e = e1 + e2 (exact to ~22 mantissa bits)
__device__ __align__(16) __half g_e1[K_CODES * D_DIM];
__device__ __align__(16) __half g_e2[K_CODES * D_DIM];

// ---------------------------------------------------------------------------
// PTX helpers (sm_80-era features only: cp.async, ldmatrix, mma.sync)
// ---------------------------------------------------------------------------
__device__ __forceinline__ uint32_t smem_u32(const void* p) {
    uint32_t a;
    asm("{ .reg .u64 t; cvta.to.shared.u64 t, %1; cvt.u32.u64 %0, t; }"
        : "=r"(a) : "l"(p));
    return a;
}

#define CP_ASYNC16(dst, src) \
    asm volatile("cp.async.cg.shared.global [%0], [%1], 16;" \
                 :: "r"(dst), "l"(src) : "memory")
#define CP_ASYNC_COMMIT() asm volatile("cp.async.commit_group;" ::: "memory")
#define CP_ASYNC_WAIT0()  asm volatile("cp.async.wait_group 0;" ::: "memory")
#define CP_ASYNC_WAIT1()  asm volatile("cp.async.wait_group 1;" ::: "memory")

__device__ __forceinline__ void ldm_x4(uint32_t* r, uint32_t addr) {
    asm volatile("ldmatrix.sync.aligned.m8n8.x4.shared.b16 {%0,%1,%2,%3}, [%4];"
        : "=r"(r[0]), "=r"(r[1]), "=r"(r[2]), "=r"(r[3]) : "r"(addr));
}

__device__ __forceinline__ void mma16816(float* c, const uint32_t* a,
                                         const uint32_t* b) {
    asm volatile(
        "mma.sync.aligned.m16n8k16.row.col.f32.f16.f16.f32 "
        "{%0,%1,%2,%3}, {%4,%5,%6,%7}, {%8,%9}, {%0,%1,%2,%3};"
        : "+f"(c[0]), "+f"(c[1]), "+f"(c[2]), "+f"(c[3])
        : "r"(a[0]), "r"(a[1]), "r"(a[2]), "r"(a[3]), "r"(b[0]), "r"(b[1]));
}

// sm_90+ vectorized global reduction (4x fewer L2 atomic ops)
__device__ __forceinline__ void red_add_v4(float* p, float4 v) {
    asm volatile("red.global.add.v4.f32 [%0], {%1, %2, %3, %4};"
                 :: "l"(p), "f"(v.x), "f"(v.y), "f"(v.z), "f"(v.w) : "memory");
}

// ---------------------------------------------------------------------------
// Zero scratch (graph replays must be deterministic)
// ---------------------------------------------------------------------------
__global__ void zero_kernel() {
    int i = blockIdx.x * blockDim.x + threadIdx.x;
    if (i < K_CODES * D_DIM) g_esum[i] = 0.0f;
    if (i < K_CODES)         g_counts[i] = 0.0f;
    if (i == 0)              g_total = 0.0f;
}

// ---------------------------------------------------------------------------
// fp16 2-limb exact split of embed
// ---------------------------------------------------------------------------
__global__ __launch_bounds__(256)
void split_e_kernel(const float* __restrict__ e) {
    const int i = blockIdx.x * 256 + threadIdx.x;   // pair index
    const int n2 = K_CODES * D_DIM / 2;
    if (i >= n2) return;
    float2 v = ((const float2*)e)[i];
    __half a1 = __float2half_rn(v.x);
    __half b1 = __float2half_rn(v.y);
    __half a2 = __float2half_rn(v.x - __half2float(a1));
    __half b2 = __float2half_rn(v.y - __half2float(b1));
    ((__half2*)g_e1)[i] = __halves2half2(a1, b1);
    ((__half2*)g_e2)[i] = __halves2half2(a2, b2);
}

// ---------------------------------------------------------------------------
// 0.5*||e_k||^2 (fp32, from original embed)
// ---------------------------------------------------------------------------
__global__ void ehn_kernel(const float* __restrict__ embed) {
    const int k = blockIdx.x;
    const int t = threadIdx.x;  // 0..63
    float4 v = *(const float4*)(embed + (size_t)k * D_DIM + t * 4);
    float s = v.x * v.x + v.y * v.y + v.z * v.z + v.w * v.w;
#pragma unroll
    for (int o = 16; o > 0; o >>= 1) s += __shfl_xor_sync(0xffffffffu, s, o);
    __shared__ float sh[2];
    if ((t & 31) == 0) sh[t >> 5] = s;
    __syncthreads();
    if (t == 0) g_ehn[k] = 0.5f * (sh[0] + sh[1]);
}

// ---------------------------------------------------------------------------
// HMMA argmin kernel — exact R9 configuration (best measured: 537.7 us).
//   256 threads, 8 warps = 4 warp_m (32 rows) x 2 warp_n (64 cols).
//   argmin_k ||x-e_k||^2 == argmax_k (x.e_k - ||e_k||^2/2).
//   x split to fp16 limbs IN-KERNEL, resident in smem (128 KB, swizzled).
//   B (embed limbs) streamed in [128 codes x 64 d] double-buffered stages.
//   64 stages; per k16 step: 3 limb products (a1b1, a1b2, a2b1).
// ---------------------------------------------------------------------------
#define A_LIMB_STRIDE 65536       // 128 rows x 512 B
#define B_OFF  131072             // A occupies [0, 128KB)
#define B_STG  32768              // per stage: 2 limbs x 128 x 128B
#define DSMEM_SZ (B_OFF + 2 * B_STG)   // 196608

__device__ __forceinline__ void issue_B(int s, uint32_t Bb, int tid) {
    const int tile = s >> 2, ch = s & 3, buf = s & 1;
#pragma unroll
    for (int i = 0; i < 8; i++) {
        const int idx = i * 256 + tid;        // 0..2047
        const int limb = idx >> 10;
        const int rem  = idx & 1023;
        const int n    = rem >> 3;            // 0..127
        const int kc   = rem & 7;             // 16B chunk within 64-d row
        const __half* src = (limb ? g_e2 : g_e1) +
            (size_t)(tile * 128 + n) * D_DIM + ch * 64 + kc * 8;
        const uint32_t dst = Bb + buf * B_STG + limb * 16384 +
            n * 128 + ((kc ^ (n & 7)) * 16);
        CP_ASYNC16(dst, src);
    }
    CP_ASYNC_COMMIT();
}

__global__ __launch_bounds__(256, 1)
void argmin_mma_kernel(const float* __restrict__ x) {
    extern __shared__ char dsm[];
    __shared__ float s_v[256];
    __shared__ int   s_i[256];

    const int tid    = threadIdx.x;
    const int wid    = tid >> 5;
    const int lane   = tid & 31;
    const int warp_m = wid & 3;     // 32 rows each
    const int warp_n = wid >> 2;    // 64 cols each (0..1)
    const int row0   = blockIdx.x * 128;

    const uint32_t Ab = smem_u32(dsm);
    const uint32_t Bb = Ab + B_OFF;

    // ---- Phase 1: load x block, split to fp16 limbs, store swizzled smem ----
    // A layout per limb: [m][512B row], 16B chunk index swizzled:
    //   swc = (chunk & 24) | ((chunk ^ m) & 7)
#pragma unroll 4
    for (int j = 0; j < 32; j++) {
        const int f  = j * 256 + tid;         // float4 index, 0..8191
        const int m  = f >> 6;                // 0..127
        const int k0 = (f & 63) * 4;          // 0..252
        float4 v = __ldg((const float4*)(x + (size_t)(row0 + m) * D_DIM + k0));
        __half hx1 = __float2half_rn(v.x), hy1 = __float2half_rn(v.y);
        __half hz1 = __float2half_rn(v.z), hw1 = __float2half_rn(v.w);
        __half hx2 = __float2half_rn(v.x - __half2float(hx1));
        __half hy2 = __float2half_rn(v.y - __half2float(hy1));
        __half hz2 = __float2half_rn(v.z - __half2float(hz1));
        __half hw2 = __float2half_rn(v.w - __half2float(hw1));
        const int chunk = k0 >> 3;
        const int swc = (chunk & 24) | ((chunk ^ m) & 7);
        const uint32_t off = (uint32_t)(m * 512 + swc * 16 + (k0 & 7) * 2);
        __half2* p1 = (__half2*)(dsm + off);
        p1[0] = __halves2half2(hx1, hy1);
        p1[1] = __halves2half2(hz1, hw1);
        __half2* p2 = (__half2*)(dsm + A_LIMB_STRIDE + off);
        p2[0] = __halves2half2(hx2, hy2);
        p2[1] = __halves2half2(hz2, hw2);
    }
    __syncthreads();

    // ---- Phase 2: main loop over 64 stages ----
    float C[2][8][4];
#pragma unroll
    for (int mf = 0; mf < 2; mf++)
#pragma unroll
        for (int nf = 0; nf < 8; nf++)
#pragma unroll
            for (int q = 0; q < 4; q++) C[mf][nf][q] = 0.0f;

    float bestv[4];
    int   besti[4];
#pragma unroll
    for (int q = 0; q < 4; q++) { bestv[q] = -3.402823466e38f; besti[q] = 0; }

    issue_B(0, Bb, tid);

    for (int s = 0; s < 64; s++) {
        const int tile = s >> 2, ch = s & 3, buf = s & 1;
        if (s < 63) { issue_B(s + 1, Bb, tid); CP_ASYNC_WAIT1(); }
        else        { CP_ASYNC_WAIT0(); }
        __syncthreads();

        const uint32_t Bs = Bb + buf * B_STG;
#pragma unroll
        for (int ks = 0; ks < 4; ks++) {
            // A fragments: [limb][mf] x4 (m16 x k16)
            uint32_t a[2][2][4];
#pragma unroll
            for (int limb = 0; limb < 2; limb++)
#pragma unroll
                for (int mf = 0; mf < 2; mf++) {
                    const int m = warp_m * 32 + mf * 16 + (lane & 15);
                    const int chunk = ch * 8 + ks * 2 + ((lane >> 4) & 1);
                    const int swc = (chunk & 24) | ((chunk ^ m) & 7);
                    ldm_x4(a[limb][mf],
                           Ab + limb * A_LIMB_STRIDE + m * 512 + swc * 16);
                }
            // B fragments: [limb][nf] x2, loaded as x4 pairs (n16 x k16)
            uint32_t b[2][8][2];
#pragma unroll
            for (int limb = 0; limb < 2; limb++)
#pragma unroll
                for (int nfp = 0; nfp < 4; nfp++) {
                    const int n = warp_n * 64 + nfp * 16 + (lane & 7) +
                                  ((lane >> 4) & 1) * 8;
                    const int kc = ks * 2 + ((lane >> 3) & 1);
                    uint32_t r[4];
                    ldm_x4(r, Bs + limb * 16384 + n * 128 +
                              ((kc ^ (n & 7)) * 16));
                    b[limb][nfp * 2    ][0] = r[0];
                    b[limb][nfp * 2    ][1] = r[1];
                    b[limb][nfp * 2 + 1][0] = r[2];
                    b[limb][nfp * 2 + 1][1] = r[3];
                }
            // 3 limb products per (mf, nf)
#pragma unroll
            for (int mf = 0; mf < 2; mf++)
#pragma unroll
                for (int nf = 0; nf < 8; nf++) {
                    mma16816(C[mf][nf], a[0][mf], b[0][nf]);
                    mma16816(C[mf][nf], a[0][mf], b[1][nf]);
                    mma16816(C[mf][nf], a[1][mf], b[0][nf]);
                }
        }

        // ---- epilogue every finished code tile (overlaps next cp.async) ----
        if (ch == 3) {
            const int cb = tile * 128 + warp_n * 64 + (lane & 3) * 2;
#pragma unroll
            for (int nf = 0; nf < 8; nf++) {
                const int col = cb + nf * 8;
                const float2 h = __ldg((const float2*)(g_ehn + col));
#pragma unroll
                for (int mf = 0; mf < 2; mf++) {
                    const int sl = mf * 2;
                    const float s0 = C[mf][nf][0] - h.x;
                    const float s1 = C[mf][nf][1] - h.y;
                    const float s2 = C[mf][nf][2] - h.x;
                    const float s3 = C[mf][nf][3] - h.y;
                    // ascending col within thread + strict > : lowest col wins
                    if (s0 > bestv[sl])     { bestv[sl] = s0;     besti[sl] = col; }
                    if (s1 > bestv[sl])     { bestv[sl] = s1;     besti[sl] = col + 1; }
                    if (s2 > bestv[sl + 1]) { bestv[sl + 1] = s2; besti[sl + 1] = col; }
                    if (s3 > bestv[sl + 1]) { bestv[sl + 1] = s3; besti[sl + 1] = col + 1; }
                    C[mf][nf][0] = 0.0f; C[mf][nf][1] = 0.0f;
                    C[mf][nf][2] = 0.0f; C[mf][nf][3] = 0.0f;
                }
            }
        }
        __syncthreads();
    }

    // ---- Final reduction ----
    // Per-row candidates live in a quartet of lanes (same lane>>2).
#pragma unroll
    for (int sl = 0; sl < 4; sl++) {
        float v = bestv[sl];
        int   ii = besti[sl];
#pragma unroll
        for (int msk = 1; msk <= 2; msk <<= 1) {
            const float ov = __shfl_xor_sync(0xffffffffu, v, msk);
            const int   oi = __shfl_xor_sync(0xffffffffu, ii, msk);
            if (ov > v || (ov == v && oi < ii)) { v = ov; ii = oi; }
        }
        if ((lane & 3) == 0) {
            const int lr = warp_m * 32 + (sl >> 1) * 16 + (sl & 1) * 8 + (lane >> 2);
            s_v[warp_n * 128 + lr] = v;
            s_i[warp_n * 128 + lr] = ii;
        }
    }
    __syncthreads();
    if (tid < 128) {
        float v0 = s_v[tid];        int i0 = s_i[tid];
        const float v1 = s_v[128 + tid];
        const int   i1 = s_i[128 + tid];
        if (v1 > v0 || (v1 == v0 && i1 < i0)) { v0 = v1; i0 = i1; }
        g_idx[row0 + tid] = i0;
    }
}

// ---------------------------------------------------------------------------
// Gather quantize rows + scatter counts/embed_sum.
// Vectorized L2 reductions (red.global.add.v4.f32): 4x fewer atomic ops.
// ---------------------------------------------------------------------------
__global__ __launch_bounds__(256)
void gather_scatter_kernel(const float* __restrict__ x,
                           const float* __restrict__ embed,
                           float* __restrict__ out) {
    const int row = blockIdx.x * 4 + (threadIdx.x >> 6);
    const int t   = threadIdx.x & 63;
    const int k   = g_idx[row];
    const int dof = t * 4;

    float4 e = __ldg((const float4*)(embed + (size_t)k * D_DIM + dof));
    *(float4*)(out + OFF_Q + (size_t)row * D_DIM + dof) = e;

    float4 xv = __ldg((const float4*)(x + (size_t)row * D_DIM + dof));
    red_add_v4(&g_esum[k * D_DIM + dof], xv);

    if (t == 0) {
        out[OFF_IND + row] = (float)k;
        atomicAdd(&g_counts[k], 1.0f);
    }
}

// ---------------------------------------------------------------------------
// Finalize 1: new_cluster_size + total (single block)
// ---------------------------------------------------------------------------
__global__ void finalize1_kernel(const float* __restrict__ cluster_size,
                                 float* __restrict__ out) {
    const int t = threadIdx.x;  // 1024 threads
    float s = 0.0f;
    for (int i = t; i < K_CODES; i += 1024) {
        const float v = cluster_size[i] * DECAY_F + OMD_F * g_counts[i];
        out[OFF_CS + i] = v;
        s += v;
    }
#pragma unroll
    for (int o = 16; o > 0; o >>= 1) s += __shfl_xor_sync(0xffffffffu, s, o);
    __shared__ float sh[32];
    if ((t & 31) == 0) sh[t >> 5] = s;
    __syncthreads();
    if (t < 32) {
        float v = sh[t];
#pragma unroll
        for (int o = 16; o > 0; o >>= 1) v += __shfl_xor_sync(0xffffffffu, v, o);
        if (t == 0) g_total = v;
    }
}

// ---------------------------------------------------------------------------
// Finalize 2: new_embed_avg + new_embed (grid = K blocks x 64 threads)
// ---------------------------------------------------------------------------
__global__ void finalize2_kernel(const float* __restrict__ embed_avg,
                                 float* __restrict__ out) {
    const int k = blockIdx.x;
    const int t = threadIdx.x;  // 0..63
    const float ncs   = out[OFF_CS + k];
    const float total = g_total;
    const float smoothed = (ncs + EPS_F) / (total + EPS_F * (float)K_CODES) * total;

    const int base = k * D_DIM + t * 4;
    float4 ea = *(const float4*)(embed_avg + base);
    float4 es = *(const float4*)(&g_esum[base]);
    float4 nav;
    nav.x = ea.x * DECAY_F + OMD_F * es.x;
    nav.y = ea.y * DECAY_F + OMD_F * es.y;
    nav.z = ea.z * DECAY_F + OMD_F * es.z;
    nav.w = ea.w * DECAY_F + OMD_F * es.w;
    *(float4*)(out + OFF_AVG + base) = nav;

    float4 ne;
    ne.x = nav.x / smoothed;
    ne.y = nav.y / smoothed;
    ne.z = nav.z / smoothed;
    ne.w = nav.w / smoothed;
    *(float4*)(out + OFF_EMB + base) = ne;
}

// ---------------------------------------------------------------------------
// Launch
// ---------------------------------------------------------------------------
extern "C" void kernel_launch(void* const* d_in, const int* in_sizes, int n_in,
                              void* d_out, int out_size) {
    const float* x         = (const float*)d_in[0];  // [B,S,D] fp32
    const float* embed     = (const float*)d_in[1];  // [K,D]
    const float* csize     = (const float*)d_in[2];  // [K]
    const float* embed_avg = (const float*)d_in[3];  // [K,D]
    float* out = (float*)d_out;

    static int smem_set = 0;
    if (!smem_set) {
        cudaFuncSetAttribute(argmin_mma_kernel,
                             cudaFuncAttributeMaxDynamicSharedMemorySize,
                             DSMEM_SZ);
        smem_set = 1;
    }

    zero_kernel<<<(K_CODES * D_DIM + 255) / 256, 256>>>();
    split_e_kernel<<<(K_CODES * D_DIM / 2 + 255) / 256, 256>>>(embed);
    ehn_kernel<<<K_CODES, 64>>>(embed);
    argmin_mma_kernel<<<N_PTS / 128, 256, DSMEM_SZ>>>(x);
    gather_scatter_kernel<<<N_PTS / 4, 256>>>(x, embed, out);
    finalize1_kernel<<<1, 1024>>>(csize, out);
    finalize2_kernel<<<K_CODES, 64>>>(embed_avg, out);
}